// round 8
// baseline (speedup 1.0000x reference)
#include <cuda_runtime.h>

#define HH 96
#define WW 128
#define CC 21
#define RR 14
#define ITERS 5
#define NBLK 96
#define NTHR 672           // 21 warps: warp = channel, lane = x-quad
#define PH (HH + 2*RR)     // 124 padded rows
#define SPW 160            // padded row floats: 14 | 128 | 14 | 4 spare

typedef unsigned long long u64;

// double-buffered blur-x(A*p)/nx output, [buf][c][padded_row][x-quad], pad rows zero
__device__ float4 g_t[2][CC][PH*32];
// cumulative per-(row, channel) flags; only warp c of block y writes flag[y][c]
__device__ unsigned g_flag[HH][CC];

__device__ __forceinline__ u64 f2pack(float lo, float hi) {
    u64 r; asm("mov.b64 %0,{%1,%2};" : "=l"(r) : "f"(lo), "f"(hi)); return r;
}
__device__ __forceinline__ u64 fma2(u64 a, u64 b, u64 c) {
    u64 d; asm("fma.rn.f32x2 %0,%1,%2,%3;" : "=l"(d) : "l"(a), "l"(b), "l"(c)); return d;
}
__device__ __forceinline__ u64 add2(u64 a, u64 b) {
    u64 d; asm("add.rn.f32x2 %0,%1,%2;" : "=l"(d) : "l"(a), "l"(b)); return d;
}
__device__ __forceinline__ void f2unpack(float& lo, float& hi, u64 v) {
    asm("mov.b64 {%0,%1},%2;" : "=f"(lo), "=f"(hi) : "l"(v));
}
__device__ __forceinline__ float rcpa(float x) {
    float r; asm("rcp.approx.f32 %0,%1;" : "=f"(r) : "f"(x)); return r;
}

__global__ void __launch_bounds__(NTHR, 1) crf_persistent(
    const float* __restrict__ un, const float* __restrict__ ws,
    const float* __restrict__ wb, const float* __restrict__ comp,
    float* __restrict__ out)
{
    // exp(-d*d/18) taps as literals -> FFMA-imm (rt=1)
    const float w[15] = {
        1.0f, 0.9459594f, 0.8007374f, 0.6065307f, 0.4111123f,
        0.2493522f, 0.1353353f, 0.0657285f, 0.0285655f, 0.0111090f,
        0.0038659f, 0.0012039f, 0.00033546f, 0.00008365f, 0.00001866f };

    __shared__ __align__(16) float  sp[CC][SPW];   // r rows; per-warp private
    __shared__ __align__(16) float4 sv[2][CC][32]; // exp(q) exchange, double-buffered
    __shared__ __align__(16) float  sA[CC][CC];    // A = compat @ (Ws+Wb)

    const int tid = threadIdx.x;
    const int c   = tid >> 5;          // warp = channel 0..20
    const int l   = tid & 31;          // lane = x-quad, pixels 4l..4l+3
    const int y   = blockIdx.x;

    // flag base: all flags equal at launch start (each replay adds exactly ITERS
    // to every flag); only self writes flag[y][c], so this read is race-free.
    const unsigned base = g_flag[y][c];

    // ---- one-time init ----
    if (l < CC) {                      // warp c computes A row c (read by own warp only)
        float a = 0.f;
        #pragma unroll
        for (int k = 0; k < CC; k++)
            a += comp[c*CC + k] * (ws[k*CC + l] + wb[k*CC + l]);
        sA[c][l] = a;
    }
    if (l < RR) { sp[c][l] = 0.f; sp[c][RR + WW + l] = 0.f; }

    // zero OWN channel's pad rows (both buffers): block y<14 owns top pad row y,
    // block y>=82 owns bottom pad row y+28. Owner is inside every reader's flag
    // window, and the warp's own release fence orders these zeros before flag 1.
    {
        int pr = -1;
        if (y < RR)            pr = y;
        else if (y >= HH - RR) pr = y + 2*RR;     // 82..95 -> 110..123
        if (pr >= 0) {
            float4 z = {0.f, 0.f, 0.f, 0.f};
            g_t[0][c][pr*32 + l] = z;
            g_t[1][c][pr*32 + l] = z;
        }
    }
    // x normalizers (truncated sums matching blur truncation)
    float4 nxi;
    {
        float s[4];
        #pragma unroll
        for (int j = 0; j < 4; j++) {
            int x = 4*l + j; float t = 0.f;
            #pragma unroll
            for (int d = -RR; d <= RR; d++) {
                int ad = d < 0 ? -d : d;
                if ((unsigned)(x + d) < WW) t += w[ad];
            }
            s[j] = 1.0f / t;
        }
        nxi.x = s[0]; nxi.y = s[1]; nxi.z = s[2]; nxi.w = s[3];
    }
    float ny = 0.f;
    #pragma unroll
    for (int d = -RR; d <= RR; d++) {
        int ad = d < 0 ? -d : d;
        if ((unsigned)(y + d) < HH) ny += w[ad];
    }
    const float nyi = 1.0f / ny;

    // unaries -> registers (q never leaves registers)
    float4 u4, q4;
    u4.x = un[(y*WW + 4*l + 0)*CC + c];
    u4.y = un[(y*WW + 4*l + 1)*CC + c];
    u4.z = un[(y*WW + 4*l + 2)*CC + c];
    u4.w = un[(y*WW + 4*l + 3)*CC + c];
    q4 = u4;
    __syncthreads();

    // ---- CRF iterations ----
    for (int it = 0; it < ITERS; it++) {
        const int b = it & 1;
        float4* tb = &g_t[b][0][0];

        // exp(q) exchange (no max-sub: q stays far below exp overflow)
        float4 e4;
        e4.x = __expf(q4.x); e4.y = __expf(q4.y);
        e4.z = __expf(q4.z); e4.w = __expf(q4.w);
        sv[b][c][l] = e4;
        __syncthreads();   // the single block-wide barrier per iteration

        // fused softmax-sum + matvec: r = (A @ e) * inv(sum e) == A @ softmax(q)
        // packed f32x2: per channel 1 LDS.128 + 1 pack + 2 add2 + 2 fma2
        u64 sm01 = 0ull, sm23 = 0ull, r01 = 0ull, r23 = 0ull;
        #pragma unroll
        for (int c2 = 0; c2 < CC; c2++) {
            ulonglong2 v = *(const ulonglong2*)&sv[b][c2][l];
            u64 ap = f2pack(sA[c][c2], sA[c][c2]);
            sm01 = add2(sm01, v.x); sm23 = add2(sm23, v.y);
            r01  = fma2(ap, v.x, r01); r23 = fma2(ap, v.y, r23);
        }
        float smx, smy, smz, smw, rx, ry, rz, rw;
        f2unpack(smx, smy, sm01); f2unpack(smz, smw, sm23);
        f2unpack(rx, ry, r01);    f2unpack(rz, rw, r23);
        sp[c][RR + 4*l + 0] = rx * rcpa(smx);
        sp[c][RR + 4*l + 1] = ry * rcpa(smy);
        sp[c][RR + 4*l + 2] = rz * rcpa(smz);
        sp[c][RR + 4*l + 3] = rw * rcpa(smw);
        __syncwarp();      // sp[c] is warp-private

        // blur-x: aligned 32-float window via 8 LDS.128, taps as immediates
        float win[32];
        {
            const float4* rowp = (const float4*)&sp[c][0];
            #pragma unroll
            for (int k = 0; k < 8; k++) {
                float4 v = rowp[l + k];
                win[4*k+0] = v.x; win[4*k+1] = v.y;
                win[4*k+2] = v.z; win[4*k+3] = v.w;
            }
        }
        float4 acc = {0.f,0.f,0.f,0.f};
        #pragma unroll
        for (int dd = 0; dd <= 28; dd++) {
            float cw = w[dd < RR ? RR - dd : dd - RR];
            acc.x += cw * win[dd];
            acc.y += cw * win[dd + 1];
            acc.z += cw * win[dd + 2];
            acc.w += cw * win[dd + 3];
        }
        acc.x *= nxi.x; acc.y *= nxi.y; acc.z *= nxi.z; acc.w *= nxi.w;
        tb[c*(PH*32) + (y + RR)*32 + l] = acc;

        // per-warp publish + wait on the 29-row neighborhood of OWN channel
        __syncwarp();
        __threadfence();                       // release own t-row (and init zeros)
        if (l == 0) atomicAdd(&g_flag[y][c], 1u);
        if (l < 2*RR + 1) {
            int yy = y - RR + l;
            if ((unsigned)yy < HH) {
                const unsigned target = base + (unsigned)(it + 1);
                volatile unsigned* pf = &g_flag[yy][c];
                while ((int)(*pf - target) < 0) { }
            }
        }
        __syncwarp();
        __threadfence();                       // acquire neighbors' t-rows

        // blur-y: 29 x LDG.128 (padded rows y..y+28), taps as immediates
        float4 a4 = {0.f,0.f,0.f,0.f};
        const float4* col = &tb[c*(PH*32) + y*32 + l];
        #pragma unroll
        for (int dd = 0; dd <= 28; dd++) {
            float4 v = __ldcg(&col[dd*32]);
            float cw = w[dd < RR ? RR - dd : dd - RR];
            a4.x += cw * v.x; a4.y += cw * v.y;
            a4.z += cw * v.z; a4.w += cw * v.w;
        }
        if (it < ITERS-1) {
            q4.x = u4.x - a4.x * nyi; q4.y = u4.y - a4.y * nyi;
            q4.z = u4.z - a4.z * nyi; q4.w = u4.w - a4.w * nyi;
        } else {
            // out layout (1, W, H, C): out[0, x, y, c]
            out[((4*l + 0)*HH + y)*CC + c] = u4.x - a4.x * nyi;
            out[((4*l + 1)*HH + y)*CC + c] = u4.y - a4.y * nyi;
            out[((4*l + 2)*HH + y)*CC + c] = u4.z - a4.z * nyi;
            out[((4*l + 3)*HH + y)*CC + c] = u4.w - a4.w * nyi;
        }
    }
}

extern "C" void kernel_launch(void* const* d_in, const int* in_sizes, int n_in,
                              void* d_out, int out_size) {
    const float* un   = (const float*)d_in[0];
    // d_in[1] (rgb) is dead: reference uses spatial_out for both message terms
    const float* ws   = (const float*)d_in[2];
    const float* wb   = (const float*)d_in[3];
    const float* comp = (const float*)d_in[4];
    crf_persistent<<<NBLK, NTHR>>>(un, ws, wb, comp, (float*)d_out);
}

// round 13
// speedup vs baseline: 1.2241x; 1.2241x over previous
#include <cuda_runtime.h>

#define HH 96
#define WW 128
#define CC 21
#define RR 14
#define ITERS 5
#define NBLK 96
#define NTHR 672           // 21 warps: warp = channel, lane = x-quad
#define PH (HH + 2*RR)     // 124 padded rows
#define SPW 160            // padded row floats: 14 | 128 | 14 | 4 spare

// double-buffered blur-x(A*p)/nx output, [buf][c][padded_row][x-quad], pad rows zero
__device__ float4 g_t[2][CC][PH*32];
// cumulative per-row completion flags (only block y writes flag[y]; replay-safe)
__device__ unsigned g_flag[HH];

__device__ __forceinline__ unsigned ldacq(const unsigned* p) {
    unsigned v;
    asm volatile("ld.acquire.gpu.global.b32 %0,[%1];" : "=r"(v) : "l"(p) : "memory");
    return v;
}

__global__ void __launch_bounds__(NTHR, 1) crf_persistent(
    const float* __restrict__ un, const float* __restrict__ ws,
    const float* __restrict__ wb, const float* __restrict__ comp,
    float* __restrict__ out)
{
    // exp(-d*d/18) taps as literals -> FFMA-imm (rt=1)
    const float w[15] = {
        1.0f, 0.9459594f, 0.8007374f, 0.6065307f, 0.4111123f,
        0.2493522f, 0.1353353f, 0.0657285f, 0.0285655f, 0.0111090f,
        0.0038659f, 0.0012039f, 0.00033546f, 0.00008365f, 0.00001866f };

    __shared__ __align__(16) float  sp[CC][SPW];  // r = A*p rows, zero-padded in x
    __shared__ __align__(16) float4 sv[CC][32];   // exp(q) exchange
    __shared__ __align__(16) float  sA[CC][CC];   // A = compat @ (Ws+Wb)

    const int tid = threadIdx.x;
    const int c   = tid >> 5;          // warp = channel 0..20
    const int l   = tid & 31;          // lane = x-quad, pixels 4l..4l+3
    const int y   = blockIdx.x;

    // flag base: all rows equal at launch start (each launch adds exactly ITERS)
    const unsigned base = g_flag[y];

    // ---- one-time init ----
    if (l < CC) {                      // warp c computes A row c
        float a = 0.f;
        #pragma unroll
        for (int k = 0; k < CC; k++)
            a += comp[c*CC + k] * (ws[k*CC + l] + wb[k*CC + l]);
        sA[c][l] = a;
    }
    if (l < RR) { sp[c][l] = 0.f; sp[c][RR + WW + l] = 0.f; }

    // zero OWN pad rows (both buffers): block y<14 owns top pad row y;
    // block y>=82 owns bottom pad row y+28. Owner is inside every reader's
    // wait window, so the iter-0 release/acquire also publishes these zeros.
    {
        int pr = -1;
        if (y < RR)            pr = y;
        else if (y >= HH - RR) pr = y + 2*RR;       // 82..95 -> 110..123
        if (pr >= 0) {
            float4 z = {0.f, 0.f, 0.f, 0.f};
            for (int i = tid; i < 2*CC*32; i += NTHR) {
                int b  = (i >= CC*32) ? 1 : 0;
                int r  = i - b*CC*32;
                int cc = r >> 5, ll = r & 31;
                g_t[b][cc][pr*32 + ll] = z;
            }
        }
    }
    // x normalizers (truncated sums matching blur truncation)
    float4 nxi;
    {
        float s[4];
        #pragma unroll
        for (int j = 0; j < 4; j++) {
            int x = 4*l + j; float t = 0.f;
            #pragma unroll
            for (int d = -RR; d <= RR; d++) {
                int ad = d < 0 ? -d : d;
                if ((unsigned)(x + d) < WW) t += w[ad];
            }
            s[j] = 1.0f / t;
        }
        nxi.x = s[0]; nxi.y = s[1]; nxi.z = s[2]; nxi.w = s[3];
    }
    float ny = 0.f;
    #pragma unroll
    for (int d = -RR; d <= RR; d++) {
        int ad = d < 0 ? -d : d;
        if ((unsigned)(y + d) < HH) ny += w[ad];
    }
    const float nyi = 1.0f / ny;

    // unaries -> registers (q never leaves registers)
    float4 u4, q4;
    u4.x = un[(y*WW + 4*l + 0)*CC + c];
    u4.y = un[(y*WW + 4*l + 1)*CC + c];
    u4.z = un[(y*WW + 4*l + 2)*CC + c];
    u4.w = un[(y*WW + 4*l + 3)*CC + c];
    q4 = u4;
    __syncthreads();

    // ---- CRF iterations ----
    for (int it = 0; it < ITERS; it++) {
        float4* tb = &g_t[it & 1][0][0];

        // exp(q) exchange (no max-sub: q stays far below exp overflow)
        float4 e4;
        e4.x = __expf(q4.x); e4.y = __expf(q4.y);
        e4.z = __expf(q4.z); e4.w = __expf(q4.w);
        sv[c][l] = e4;
        __syncthreads();

        // fused softmax-sum + matvec: r = (A @ e) * inv(sum e) == A @ softmax(q)
        float4 sm = {0.f,0.f,0.f,0.f}, r4 = {0.f,0.f,0.f,0.f};
        #pragma unroll
        for (int c2 = 0; c2 < CC; c2++) {
            float4 v = sv[c2][l];
            float  a = sA[c][c2];
            sm.x += v.x; sm.y += v.y; sm.z += v.z; sm.w += v.w;
            r4.x += a*v.x; r4.y += a*v.y; r4.z += a*v.z; r4.w += a*v.w;
        }
        sp[c][RR + 4*l + 0] = r4.x * __frcp_rn(sm.x);
        sp[c][RR + 4*l + 1] = r4.y * __frcp_rn(sm.y);
        sp[c][RR + 4*l + 2] = r4.z * __frcp_rn(sm.z);
        sp[c][RR + 4*l + 3] = r4.w * __frcp_rn(sm.w);
        __syncthreads();

        // blur-x: aligned 32-float window via 8 LDS.128, taps as immediates
        float win[32];
        {
            const float4* rowp = (const float4*)&sp[c][0];
            #pragma unroll
            for (int k = 0; k < 8; k++) {
                float4 v = rowp[l + k];
                win[4*k+0] = v.x; win[4*k+1] = v.y;
                win[4*k+2] = v.z; win[4*k+3] = v.w;
            }
        }
        float4 acc = {0.f,0.f,0.f,0.f};
        #pragma unroll
        for (int dd = 0; dd <= 28; dd++) {
            float cw = w[dd < RR ? RR - dd : dd - RR];
            acc.x += cw * win[dd];
            acc.y += cw * win[dd + 1];
            acc.z += cw * win[dd + 2];
            acc.w += cw * win[dd + 3];
        }
        acc.x *= nxi.x; acc.y *= nxi.y; acc.z *= nxi.z; acc.w *= nxi.w;
        tb[c*(PH*32) + (y + RR)*32 + l] = acc;

        // publish own row (release), wait for the 29-row neighborhood (acquire).
        // hb chain: all warps' STG -> bar.sync -> tid0 fence+bump -> remote
        // acquire-poll -> bar.sync -> that block's readers. Single fence total.
        __syncthreads();
        if (tid == 0) {
            asm volatile("fence.acq_rel.gpu;" ::: "memory");
            atomicAdd(&g_flag[y], 1u);
        }
        if (tid < 2*RR + 1) {
            int yy = y - RR + tid;
            if ((unsigned)yy < HH) {
                const unsigned target = base + (unsigned)(it + 1);
                while ((int)(ldacq(&g_flag[yy]) - target) < 0) { }
            }
        }
        __syncthreads();

        // blur-y: 29 x LDG.128 (padded rows y..y+28); message lands directly
        float4 a4 = {0.f,0.f,0.f,0.f};
        const float4* col = &tb[c*(PH*32) + y*32 + l];
        #pragma unroll
        for (int dd = 0; dd <= 28; dd++) {
            float4 v = __ldcg(&col[dd*32]);
            float cw = w[dd < RR ? RR - dd : dd - RR];
            a4.x += cw * v.x; a4.y += cw * v.y;
            a4.z += cw * v.z; a4.w += cw * v.w;
        }
        if (it < ITERS-1) {
            q4.x = u4.x - a4.x * nyi; q4.y = u4.y - a4.y * nyi;
            q4.z = u4.z - a4.z * nyi; q4.w = u4.w - a4.w * nyi;
        } else {
            // out layout (1, W, H, C): out[0, x, y, c]
            out[((4*l + 0)*HH + y)*CC + c] = u4.x - a4.x * nyi;
            out[((4*l + 1)*HH + y)*CC + c] = u4.y - a4.y * nyi;
            out[((4*l + 2)*HH + y)*CC + c] = u4.z - a4.z * nyi;
            out[((4*l + 3)*HH + y)*CC + c] = u4.w - a4.w * nyi;
        }
    }
}

extern "C" void kernel_launch(void* const* d_in, const int* in_sizes, int n_in,
                              void* d_out, int out_size) {
    const float* un   = (const float*)d_in[0];
    // d_in[1] (rgb) is dead: reference uses spatial_out for both message terms
    const float* ws   = (const float*)d_in[2];
    const float* wb   = (const float*)d_in[3];
    const float* comp = (const float*)d_in[4];
    crf_persistent<<<NBLK, NTHR>>>(un, ws, wb, comp, (float*)d_out);
}